// round 14
// baseline (speedup 1.0000x reference)
#include <cuda_runtime.h>
#include <cuda_fp16.h>
#include <cstdint>
#include <math.h>

// Problem constants
#define BB      4
#define SS      2048
#define CC      1024
#define HH      16
#define DD      64
#define NSTATE  1024
#define WIN     256
#define SCALE_INV 0.125f   // 1/sqrt(64)

// ---------------------------------------------------------------------------
// Scratch (device globals; no runtime allocation)
// Pure fp16 1-pass pipeline (error model validated R7-R13: ~4.6e-4 total).
// ---------------------------------------------------------------------------
__device__ __half g_xh[BB * SS * CC];
__device__ __half g_wqh[3 * NSTATE * CC];
__device__ __half g_wph[CC * NSTATE];

// Q (pre-scaled by SCALE_INV), K, V: fp16, [B,H,S,D]
__device__ __half g_qh[BB * HH * SS * DD];
__device__ __half g_kh[BB * HH * SS * DD];
__device__ __half g_vh[BB * HH * SS * DD];

__device__ __half g_ch[BB * SS * NSTATE];   // ctx fp16

// ---------------------------------------------------------------------------
// PTX helpers (compute_80-safe: ldmatrix / mma.sync / cp.async)
// ---------------------------------------------------------------------------
__device__ __forceinline__ uint32_t smem_u32(const void* p) {
    uint32_t a;
    asm("{ .reg .u64 t; cvta.to.shared.u64 t, %1; cvt.u32.u64 %0, t; }"
        : "=r"(a) : "l"(p));
    return a;
}

#define CP_ASYNC16(dst, src) \
    asm volatile("cp.async.cg.shared.global [%0], [%1], 16;" \
        :: "r"(dst), "l"(src) : "memory")
#define CP_COMMIT() asm volatile("cp.async.commit_group;" ::: "memory")
#define CP_WAIT(n)  asm volatile("cp.async.wait_group %0;" :: "n"(n) : "memory")

#define LDSM_X4(r0, r1, r2, r3, addr) \
    asm volatile("ldmatrix.sync.aligned.m8n8.x4.shared.b16 {%0,%1,%2,%3}, [%4];" \
        : "=r"(r0), "=r"(r1), "=r"(r2), "=r"(r3) : "r"(addr))
#define LDSM_X4_T(r0, r1, r2, r3, addr) \
    asm volatile("ldmatrix.sync.aligned.m8n8.x4.trans.shared.b16 {%0,%1,%2,%3}, [%4];" \
        : "=r"(r0), "=r"(r1), "=r"(r2), "=r"(r3) : "r"(addr))

__device__ __forceinline__ void mma_fp16(float* c, const uint32_t* a,
                                         uint32_t b0, uint32_t b1) {
    asm volatile(
        "mma.sync.aligned.m16n8k16.row.col.f32.f16.f16.f32 "
        "{%0,%1,%2,%3}, {%4,%5,%6,%7}, {%8,%9}, {%0,%1,%2,%3};"
        : "+f"(c[0]), "+f"(c[1]), "+f"(c[2]), "+f"(c[3])
        : "r"(a[0]), "r"(a[1]), "r"(a[2]), "r"(a[3]), "r"(b0), "r"(b1));
}

__device__ __forceinline__ uint32_t pack_hi(float a, float b) {
    __half2 h = __floats2half2_rn(a, b);
    return *reinterpret_cast<uint32_t*>(&h);
}

// ---------------------------------------------------------------------------
// fused fp32 -> fp16 conversion for x, W_qkv, W_proj
// ---------------------------------------------------------------------------
#define XQ4   (BB * SS * CC / 4)
#define WQ4   (3 * NSTATE * CC / 4)
#define WP4   (CC * NSTATE / 4)

__global__ void split_all(const float* __restrict__ x,
                          const float* __restrict__ wq,
                          const float* __restrict__ wp)
{
    int i = blockIdx.x * blockDim.x + threadIdx.x;
    if (i >= XQ4 + WQ4 + WP4) return;

    const float* src;
    __half* dst;
    int j;
    if (i < XQ4)            { src = x;  dst = g_xh;  j = i; }
    else if (i < XQ4 + WQ4) { src = wq; dst = g_wqh; j = i - XQ4; }
    else                    { src = wp; dst = g_wph; j = i - XQ4 - WQ4; }
    float4 f = reinterpret_cast<const float4*>(src)[j];
    reinterpret_cast<uint32_t*>(dst)[2 * j]     = pack_hi(f.x, f.y);
    reinterpret_cast<uint32_t*>(dst)[2 * j + 1] = pack_hi(f.z, f.w);
}

// ---------------------------------------------------------------------------
// HMMA GEMM: C = A*B^T + bias, fp16 inputs, fp32 accum, single pass.
// CTA tile 128x256, K-chunk 64, 8 warps (2 M x 4 N), WARP TILE 64x64.
// Big warp tile doubles MMA:LDSM ratio (32 MMA : 8 LDSM per k16 step) so
// the smem crossbar (128 KB/chunk for 2.1 M-MAC) stops co-binding with the
// tensor pipe. 1 CTA/SM (regs ~190); latency hidden inside each warp's
// fat instruction stream. 2-stage cp.async double buffer, single sync.
// ---------------------------------------------------------------------------
#define ROWB    144            // bytes per SMEM row (64 fp16 = 128B + 16B pad)
#define TILEA   (128 * ROWB)   // 18432 B
#define TILEBB  (256 * ROWB)   // 36864 B
#define BUFG    (TILEA + TILEBB)
#define NCHK    (CC / 64)      // 16 K-chunks

template <int MODE>
__global__ __launch_bounds__(256, 1)
void hmma_gemm(const float* __restrict__ bias, float* __restrict__ out)
{
    extern __shared__ char dynsmem[];
    const uint32_t tb = smem_u32(dynsmem);

    const int tid  = threadIdx.x;
    const int wid  = tid >> 5;
    const int lane = tid & 31;
    const int m0 = blockIdx.y * 128;
    const int n0 = blockIdx.x * 256;

    const int wm = wid >> 2;           // 0..1
    const int wn = wid & 3;            // 0..3
    const int mbase = wm * 64;
    const int nbase = wn * 64;

    const int rowA  = lane & 15;
    const int koffA = (lane >> 4) * 16;
    const int rowB  = (lane & 7) + ((lane >> 4) & 1) * 8;
    const int koffB = ((lane >> 3) & 1) * 16;

    const __half* srcA = ((MODE == 0) ? g_xh : g_ch) + (size_t)m0 * CC;
    const __half* srcB = ((MODE == 0) ? g_wqh : g_wph) + (size_t)n0 * CC;

    const int ldrow0 = tid >> 3;      // 0..31
    const int lduc   = tid & 7;       // 8 x 16B columns

    float c[4][8][4];
    #pragma unroll
    for (int i = 0; i < 4; i++)
        #pragma unroll
        for (int j = 0; j < 8; j++)
            #pragma unroll
            for (int q = 0; q < 4; q++) c[i][j][q] = 0.f;

    auto issue = [&](int ch) {
        const int k0 = ch * 64;
        const uint32_t dstb = tb + (ch & 1) * BUFG;
        #pragma unroll
        for (int it = 0; it < 4; ++it) {                 // A: 128 rows
            const int row = ldrow0 + it * 32;
            CP_ASYNC16(dstb + row * ROWB + lduc * 16,
                       srcA + (size_t)row * CC + k0 + lduc * 8);
        }
        #pragma unroll
        for (int it = 0; it < 8; ++it) {                 // B: 256 rows
            const int row = ldrow0 + it * 32;
            CP_ASYNC16(dstb + TILEA + row * ROWB + lduc * 16,
                       srcB + (size_t)row * CC + k0 + lduc * 8);
        }
    };

    issue(0);
    CP_COMMIT();

    for (int ch = 0; ch < NCHK; ++ch) {
        CP_WAIT(0);
        __syncthreads();
        if (ch + 1 < NCHK) {
            issue(ch + 1);
            CP_COMMIT();
        }

        const uint32_t buf = tb + (ch & 1) * BUFG;
        const uint32_t Ah = buf;
        const uint32_t Bh = buf + TILEA;

        #pragma unroll
        for (int ks = 0; ks < 4; ++ks) {
            const int kb = ks * 32;

            uint32_t ah[4][4];
            #pragma unroll
            for (int mt = 0; mt < 4; ++mt) {
                const uint32_t off = (mbase + mt * 16 + rowA) * ROWB + kb + koffA;
                LDSM_X4(ah[mt][0], ah[mt][1], ah[mt][2], ah[mt][3], Ah + off);
            }
            uint32_t bh[4][4];
            #pragma unroll
            for (int np = 0; np < 4; ++np) {
                const uint32_t off = (nbase + np * 16 + rowB) * ROWB + kb + koffB;
                LDSM_X4(bh[np][0], bh[np][1], bh[np][2], bh[np][3], Bh + off);
            }

            #pragma unroll
            for (int mt = 0; mt < 4; ++mt) {
                #pragma unroll
                for (int nt = 0; nt < 8; ++nt) {
                    const int np = nt >> 1;
                    const int w2 = (nt & 1) * 2;
                    mma_fp16(c[mt][nt], ah[mt], bh[np][w2], bh[np][w2 + 1]);
                }
            }
        }
    }

    // ---- epilogue ----
    const int quad = lane >> 2;
    const int tq   = lane & 3;

    if (MODE == 0) {
        const int sec = n0 >> 10;                     // 0=q, 1=k, 2=v
        const int h   = ((n0 + nbase) & 1023) >> 6;
        const float sc = (sec == 0) ? SCALE_INV : 1.0f;
        __half* dst = (sec == 0) ? g_qh : (sec == 1) ? g_kh : g_vh;
        #pragma unroll
        for (int mt = 0; mt < 4; ++mt) {
            #pragma unroll
            for (int half = 0; half < 2; ++half) {
                const int m = m0 + mbase + mt * 16 + quad + half * 8;
                const int b = m >> 11;
                const int s = m & 2047;
                const size_t rowp = ((size_t)((b * HH + h) * SS + s)) * DD;
                #pragma unroll
                for (int nt = 0; nt < 8; ++nt) {
                    const int n = n0 + nbase + nt * 8 + tq * 2;
                    const int d = nt * 8 + tq * 2;
                    const float2 bv = *(const float2*)&bias[n];
                    *(uint32_t*)&dst[rowp + d] =
                        pack_hi((c[mt][nt][half * 2 + 0] + bv.x) * sc,
                                (c[mt][nt][half * 2 + 1] + bv.y) * sc);
                }
            }
        }
    } else {
        #pragma unroll
        for (int mt = 0; mt < 4; ++mt) {
            #pragma unroll
            for (int half = 0; half < 2; ++half) {
                const int m = m0 + mbase + mt * 16 + quad + half * 8;
                #pragma unroll
                for (int nt = 0; nt < 8; ++nt) {
                    const int n = n0 + nbase + nt * 8 + tq * 2;
                    const float2 bv = *(const float2*)&bias[n];
                    float2 o;
                    o.x = c[mt][nt][half * 2 + 0] + bv.x;
                    o.y = c[mt][nt][half * 2 + 1] + bv.y;
                    *(float2*)&out[(size_t)m * NSTATE + n] = o;
                }
            }
        }
    }
}

// ---------------------------------------------------------------------------
// HMMA windowed attention, single-pass fp16: S = Q*K^T, ctx = P*V.
// 1 CTA per (qt, h, b); 4 warps. K/V double buffer via cp.async.
// ---------------------------------------------------------------------------
#define AP 144   // SMEM row pitch bytes (64 fp16 = 128B + 16B pad)

__global__ __launch_bounds__(128)
void attn_hmma()
{
    extern __shared__ char smraw[];
    const uint32_t sb   = smem_u32(smraw);
    const uint32_t Qh_s = sb;
    const uint32_t KVb  = sb + 64 * AP;   // [2 bufs][Kh, Vh][64*AP]

    const int tid  = threadIdx.x;
    const int lane = tid & 31;
    const int wid  = tid >> 5;
    const int qt = blockIdx.x;
    const int h  = blockIdx.y;
    const int b  = blockIdx.z;

    const size_t base = ((size_t)(b * HH + h) * SS) * DD;
    const char* qhp = (const char*)(g_qh + base) + (size_t)qt * 64 * 128;
    const char* kvsrc[2] = { (const char*)(g_kh + base), (const char*)(g_vh + base) };

    const int lr  = tid >> 1;
    const int lcb = (tid & 1) * 64;

    #pragma unroll
    for (int i = 0; i < 4; i++)
        CP_ASYNC16(Qh_s + lr * AP + lcb + i * 16, qhp + lr * 128 + lcb + i * 16);

    auto loadKV = [&](int kt, int p) {
        const uint32_t d0 = KVb + p * (2 * 64 * AP);
        #pragma unroll
        for (int t = 0; t < 2; t++)
            #pragma unroll
            for (int i = 0; i < 4; i++)
                CP_ASYNC16(d0 + t * 64 * AP + lr * AP + lcb + i * 16,
                           kvsrc[t] + ((size_t)kt * 64 + lr) * 128 + lcb + i * 16);
    };

    const int kt0 = (qt >= 4) ? (qt - 4) : 0;
    const int nkt = qt - kt0 + 1;
    loadKV(kt0, 0);
    CP_COMMIT();

    const int rowA = lane & 15, kbA = (lane >> 4) * 16;
    const int rowB = (lane & 7) + ((lane >> 4) & 1) * 8, kbB = ((lane >> 3) & 1) * 16;
    const int rowV = (lane & 7) + ((lane >> 3) & 1) * 8, cbV = ((lane >> 4) & 1) * 16;
    const int quad = lane >> 2, tq = lane & 3;

    uint32_t qah[4][4];
    float ctx[8][4];
    #pragma unroll
    for (int i = 0; i < 8; i++)
        #pragma unroll
        for (int j = 0; j < 4; j++) ctx[i][j] = 0.f;
    float rs0 = 0.f, rs1 = 0.f;

    for (int it = 0; it < nkt; ++it) {
        const int kt = kt0 + it;
        const int p  = it & 1;
        CP_WAIT(0);
        __syncthreads();
        if (it + 1 < nkt) {
            loadKV(kt + 1, p ^ 1);
            CP_COMMIT();
        }

        if (it == 0) {
            #pragma unroll
            for (int ks = 0; ks < 4; ks++) {
                const uint32_t off = (wid * 16 + rowA) * AP + ks * 32 + kbA;
                LDSM_X4(qah[ks][0], qah[ks][1], qah[ks][2], qah[ks][3], Qh_s + off);
            }
        }

        const uint32_t Kh = KVb + p * (2 * 64 * AP);
        const uint32_t Vh = Kh + 64 * AP;

        // ---- S = Q K^T ----
        float s[8][4];
        #pragma unroll
        for (int i = 0; i < 8; i++)
            #pragma unroll
            for (int j = 0; j < 4; j++) s[i][j] = 0.f;

        #pragma unroll
        for (int ks = 0; ks < 4; ks++) {
            #pragma unroll
            for (int h2 = 0; h2 < 2; ++h2) {
                uint32_t kh[2][4];
                #pragma unroll
                for (int ppl = 0; ppl < 2; ppl++) {
                    const int pp = h2 * 2 + ppl;
                    const uint32_t off = (pp * 16 + rowB) * AP + ks * 32 + kbB;
                    LDSM_X4(kh[ppl][0], kh[ppl][1], kh[ppl][2], kh[ppl][3], Kh + off);
                }
                #pragma unroll
                for (int ntl = 0; ntl < 4; ntl++) {
                    const int nt = h2 * 4 + ntl;
                    const int npl = ntl >> 1, w2 = (ntl & 1) * 2;
                    mma_fp16(s[nt], qah[ks], kh[npl][w2], kh[npl][w2 + 1]);
                }
            }
        }

        // ---- mask + exp + pack P into PV A-fragments ----
        uint32_t pah[4][4];
        const int i0 = qt * 64 + wid * 16 + quad;
        const int jb = kt * 64 + tq * 2;
        #pragma unroll
        for (int nt = 0; nt < 8; nt++) {
            const int j0 = jb + nt * 8;
            const int j1 = j0 + 1;
            float e0 = __expf(s[nt][0]);
            float e1 = __expf(s[nt][1]);
            float e2 = __expf(s[nt][2]);
            float e3 = __expf(s[nt][3]);
            { int df = i0 - j0;     if (df < 0 || df >= WIN) e0 = 0.f; }
            { int df = i0 - j1;     if (df < 0 || df >= WIN) e1 = 0.f; }
            { int df = i0 + 8 - j0; if (df < 0 || df >= WIN) e2 = 0.f; }
            { int df = i0 + 8 - j1; if (df < 0 || df >= WIN) e3 = 0.f; }
            rs0 += e0 + e1;
            rs1 += e2 + e3;
            const int ks = nt >> 1, r2 = (nt & 1) * 2;
            pah[ks][r2]     = pack_hi(e0, e1);
            pah[ks][r2 + 1] = pack_hi(e2, e3);
        }

        // ---- ctx += P V ----
        #pragma unroll
        for (int ks = 0; ks < 4; ks++) {
            #pragma unroll
            for (int h2 = 0; h2 < 2; ++h2) {
                uint32_t vh[2][4];
                #pragma unroll
                for (int ppl = 0; ppl < 2; ppl++) {
                    const int pp = h2 * 2 + ppl;
                    const uint32_t off = (ks * 16 + rowV) * AP + pp * 32 + cbV;
                    LDSM_X4_T(vh[ppl][0], vh[ppl][1], vh[ppl][2], vh[ppl][3], Vh + off);
                }
                #pragma unroll
                for (int ntl = 0; ntl < 4; ntl++) {
                    const int nt = h2 * 4 + ntl;
                    const int npl = ntl >> 1, w2 = (ntl & 1) * 2;
                    mma_fp16(ctx[nt], pah[ks], vh[npl][w2], vh[npl][w2 + 1]);
                }
            }
        }
    }

    rs0 += __shfl_xor_sync(0xFFFFFFFFu, rs0, 1);
    rs0 += __shfl_xor_sync(0xFFFFFFFFu, rs0, 2);
    rs1 += __shfl_xor_sync(0xFFFFFFFFu, rs1, 1);
    rs1 += __shfl_xor_sync(0xFFFFFFFFu, rs1, 2);
    const float inv0 = 1.0f / rs0;
    const float inv1 = 1.0f / rs1;

    const int s0 = qt * 64 + wid * 16 + quad;
    #pragma unroll
    for (int nt = 0; nt < 8; nt++) {
        const int d = nt * 8 + tq * 2;
        const size_t ix0 = ((size_t)(b * SS) + s0) * NSTATE + h * 64 + d;
        const size_t ix1 = ix0 + (size_t)8 * NSTATE;
        *(uint32_t*)&g_ch[ix0] = pack_hi(ctx[nt][0] * inv0, ctx[nt][1] * inv0);
        *(uint32_t*)&g_ch[ix1] = pack_hi(ctx[nt][2] * inv1, ctx[nt][3] * inv1);
    }
}

// ---------------------------------------------------------------------------
// Launch
// ---------------------------------------------------------------------------
extern "C" void kernel_launch(void* const* d_in, const int* in_sizes, int n_in,
                              void* d_out, int out_size)
{
    const float* x      = (const float*)d_in[0];
    const float* W_qkv  = (const float*)d_in[1];
    const float* b_qkv  = (const float*)d_in[2];
    const float* W_proj = (const float*)d_in[3];
    const float* b_proj = (const float*)d_in[4];
    float* out = (float*)d_out;

    const int GEMM_SMEM = 2 * BUFG;              // 110592 B (2 stages)
    const int ATTN_SMEM = (1 + 4) * 64 * AP;     // 46080 B
    cudaFuncSetAttribute(hmma_gemm<0>, cudaFuncAttributeMaxDynamicSharedMemorySize, GEMM_SMEM);
    cudaFuncSetAttribute(hmma_gemm<1>, cudaFuncAttributeMaxDynamicSharedMemorySize, GEMM_SMEM);
    cudaFuncSetAttribute(attn_hmma, cudaFuncAttributeMaxDynamicSharedMemorySize, ATTN_SMEM);

    const int NSPLIT = XQ4 + WQ4 + WP4;
    split_all<<<(NSPLIT + 255) / 256, 256>>>(x, W_qkv, W_proj);

    // QKV GEMM: [8192,1024] x [3072,1024]^T -> Q (scaled), K, V fp16
    hmma_gemm<0><<<dim3(3072 / 256, 8192 / 128), 256, GEMM_SMEM>>>(b_qkv, nullptr);

    // windowed attention -> ctx fp16
    attn_hmma<<<dim3(SS / 64, HH, BB), 128, ATTN_SMEM>>>();

    // proj GEMM: [8192,1024] x [1024,1024]^T -> out
    hmma_gemm<1><<<dim3(1024 / 256, 8192 / 128), 256, GEMM_SMEM>>>(b_proj, out);
}

// round 15
// speedup vs baseline: 1.0866x; 1.0866x over previous
#include <cuda_runtime.h>
#include <cuda_fp16.h>
#include <cstdint>
#include <math.h>

// Problem constants
#define BB      4
#define SS      2048
#define CC      1024
#define HH      16
#define DD      64
#define NSTATE  1024
#define WIN     256
#define SCALE_INV 0.125f   // 1/sqrt(64)

// ---------------------------------------------------------------------------
// Scratch (device globals; no runtime allocation)
// Pure fp16 1-pass pipeline (error model validated R7-R14: ~4.6e-4 total).
// ---------------------------------------------------------------------------
__device__ __half g_xh[BB * SS * CC];
__device__ __half g_wqh[3 * NSTATE * CC];
__device__ __half g_wph[CC * NSTATE];

// Q (pre-scaled by SCALE_INV), K, V: fp16, [B,H,S,D]
__device__ __half g_qh[BB * HH * SS * DD];
__device__ __half g_kh[BB * HH * SS * DD];
__device__ __half g_vh[BB * HH * SS * DD];

__device__ __half g_ch[BB * SS * NSTATE];   // ctx fp16

// ---------------------------------------------------------------------------
// PTX helpers (compute_80-safe: ldmatrix / mma.sync / cp.async)
// ---------------------------------------------------------------------------
__device__ __forceinline__ uint32_t smem_u32(const void* p) {
    uint32_t a;
    asm("{ .reg .u64 t; cvta.to.shared.u64 t, %1; cvt.u32.u64 %0, t; }"
        : "=r"(a) : "l"(p));
    return a;
}

#define CP_ASYNC16(dst, src) \
    asm volatile("cp.async.cg.shared.global [%0], [%1], 16;" \
        :: "r"(dst), "l"(src) : "memory")
#define CP_COMMIT() asm volatile("cp.async.commit_group;" ::: "memory")
#define CP_WAIT(n)  asm volatile("cp.async.wait_group %0;" :: "n"(n) : "memory")

#define LDSM_X4(r0, r1, r2, r3, addr) \
    asm volatile("ldmatrix.sync.aligned.m8n8.x4.shared.b16 {%0,%1,%2,%3}, [%4];" \
        : "=r"(r0), "=r"(r1), "=r"(r2), "=r"(r3) : "r"(addr))
#define LDSM_X4_T(r0, r1, r2, r3, addr) \
    asm volatile("ldmatrix.sync.aligned.m8n8.x4.trans.shared.b16 {%0,%1,%2,%3}, [%4];" \
        : "=r"(r0), "=r"(r1), "=r"(r2), "=r"(r3) : "r"(addr))

__device__ __forceinline__ void mma_fp16(float* c, const uint32_t* a,
                                         uint32_t b0, uint32_t b1) {
    asm volatile(
        "mma.sync.aligned.m16n8k16.row.col.f32.f16.f16.f32 "
        "{%0,%1,%2,%3}, {%4,%5,%6,%7}, {%8,%9}, {%0,%1,%2,%3};"
        : "+f"(c[0]), "+f"(c[1]), "+f"(c[2]), "+f"(c[3])
        : "r"(a[0]), "r"(a[1]), "r"(a[2]), "r"(a[3]), "r"(b0), "r"(b1));
}

__device__ __forceinline__ uint32_t pack_hi(float a, float b) {
    __half2 h = __floats2half2_rn(a, b);
    return *reinterpret_cast<uint32_t*>(&h);
}

// ---------------------------------------------------------------------------
// fused fp32 -> fp16 conversion for x, W_qkv, W_proj
// ---------------------------------------------------------------------------
#define XQ4   (BB * SS * CC / 4)
#define WQ4   (3 * NSTATE * CC / 4)
#define WP4   (CC * NSTATE / 4)

__global__ void split_all(const float* __restrict__ x,
                          const float* __restrict__ wq,
                          const float* __restrict__ wp)
{
    int i = blockIdx.x * blockDim.x + threadIdx.x;
    if (i >= XQ4 + WQ4 + WP4) return;

    const float* src;
    __half* dst;
    int j;
    if (i < XQ4)            { src = x;  dst = g_xh;  j = i; }
    else if (i < XQ4 + WQ4) { src = wq; dst = g_wqh; j = i - XQ4; }
    else                    { src = wp; dst = g_wph; j = i - XQ4 - WQ4; }
    float4 f = reinterpret_cast<const float4*>(src)[j];
    reinterpret_cast<uint32_t*>(dst)[2 * j]     = pack_hi(f.x, f.y);
    reinterpret_cast<uint32_t*>(dst)[2 * j + 1] = pack_hi(f.z, f.w);
}

// ---------------------------------------------------------------------------
// HMMA GEMM: C = A*B^T + bias, fp16 inputs, fp32 accum, single pass.
// CTA tile 128x128, 128 THREADS (4 warps, 2M x 2N), WARP TILE 64x64,
// 2 CTAs/SM. Combines R14's 4:1 MMA:LDSM intensity with R13's dual-CTA
// phase overlap: 8 fat warps per SM from two desynchronized CTAs.
// K-chunk 64, 2-stage cp.async double buffer, single barrier per chunk.
// ---------------------------------------------------------------------------
#define ROWB   144           // bytes per SMEM row (64 fp16 = 128B + 16B pad)
#define TILEB  (128 * ROWB)  // 18432 B per operand tile
#define BUFG   (2 * TILEB)   // A, B per stage
#define NCHK   (CC / 64)     // 16 K-chunks

template <int MODE>
__global__ __launch_bounds__(128, 2)
void hmma_gemm(const float* __restrict__ bias, float* __restrict__ out)
{
    extern __shared__ char dynsmem[];
    const uint32_t tb = smem_u32(dynsmem);

    const int tid  = threadIdx.x;
    const int wid  = tid >> 5;
    const int lane = tid & 31;
    const int m0 = blockIdx.y * 128;
    const int n0 = blockIdx.x * 128;

    const int wm = wid >> 1;           // 0..1
    const int wn = wid & 1;            // 0..1
    const int mbase = wm * 64;
    const int nbase = wn * 64;

    const int rowA  = lane & 15;
    const int koffA = (lane >> 4) * 16;
    const int rowB  = (lane & 7) + ((lane >> 4) & 1) * 8;
    const int koffB = ((lane >> 3) & 1) * 16;

    const __half* srcA = ((MODE == 0) ? g_xh : g_ch) + (size_t)m0 * CC;
    const __half* srcB = ((MODE == 0) ? g_wqh : g_wph) + (size_t)n0 * CC;

    const int ldrow0 = tid >> 3;      // 0..15
    const int lduc   = tid & 7;       // 8 x 16B columns

    float c[4][8][4];
    #pragma unroll
    for (int i = 0; i < 4; i++)
        #pragma unroll
        for (int j = 0; j < 8; j++)
            #pragma unroll
            for (int q = 0; q < 4; q++) c[i][j][q] = 0.f;

    auto issue = [&](int ch) {
        const int k0 = ch * 64;
        const uint32_t dstb = tb + (ch & 1) * BUFG;
        #pragma unroll
        for (int it = 0; it < 16; ++it) {
            const int tile = it >> 3;
            const int row  = ldrow0 + (it & 7) * 16;
            const __half* s = (tile ? srcB : srcA) + (size_t)row * CC + k0 + lduc * 8;
            const uint32_t d = dstb + tile * TILEB + row * ROWB + lduc * 16;
            CP_ASYNC16(d, s);
        }
    };

    issue(0);
    CP_COMMIT();

    for (int ch = 0; ch < NCHK; ++ch) {
        CP_WAIT(0);
        __syncthreads();
        if (ch + 1 < NCHK) {
            issue(ch + 1);
            CP_COMMIT();
        }

        const uint32_t buf = tb + (ch & 1) * BUFG;
        const uint32_t Ah = buf;
        const uint32_t Bh = buf + TILEB;

        #pragma unroll
        for (int ks = 0; ks < 4; ++ks) {
            const int kb = ks * 32;

            uint32_t ah[4][4];
            #pragma unroll
            for (int mt = 0; mt < 4; ++mt) {
                const uint32_t off = (mbase + mt * 16 + rowA) * ROWB + kb + koffA;
                LDSM_X4(ah[mt][0], ah[mt][1], ah[mt][2], ah[mt][3], Ah + off);
            }
            uint32_t bh[4][4];
            #pragma unroll
            for (int np = 0; np < 4; ++np) {
                const uint32_t off = (nbase + np * 16 + rowB) * ROWB + kb + koffB;
                LDSM_X4(bh[np][0], bh[np][1], bh[np][2], bh[np][3], Bh + off);
            }

            #pragma unroll
            for (int mt = 0; mt < 4; ++mt) {
                #pragma unroll
                for (int nt = 0; nt < 8; ++nt) {
                    const int np = nt >> 1;
                    const int w2 = (nt & 1) * 2;
                    mma_fp16(c[mt][nt], ah[mt], bh[np][w2], bh[np][w2 + 1]);
                }
            }
        }
    }

    // ---- epilogue ----
    const int quad = lane >> 2;
    const int tq   = lane & 3;

    if (MODE == 0) {
        const int sec = n0 >> 10;                     // 0=q, 1=k, 2=v
        const int h   = ((n0 + nbase) & 1023) >> 6;
        const float sc = (sec == 0) ? SCALE_INV : 1.0f;
        __half* dst = (sec == 0) ? g_qh : (sec == 1) ? g_kh : g_vh;
        #pragma unroll
        for (int mt = 0; mt < 4; ++mt) {
            #pragma unroll
            for (int half = 0; half < 2; ++half) {
                const int m = m0 + mbase + mt * 16 + quad + half * 8;
                const int b = m >> 11;
                const int s = m & 2047;
                const size_t rowp = ((size_t)((b * HH + h) * SS + s)) * DD;
                #pragma unroll
                for (int nt = 0; nt < 8; ++nt) {
                    const int n = n0 + nbase + nt * 8 + tq * 2;
                    const int d = nt * 8 + tq * 2;
                    const float2 bv = *(const float2*)&bias[n];
                    *(uint32_t*)&dst[rowp + d] =
                        pack_hi((c[mt][nt][half * 2 + 0] + bv.x) * sc,
                                (c[mt][nt][half * 2 + 1] + bv.y) * sc);
                }
            }
        }
    } else {
        #pragma unroll
        for (int mt = 0; mt < 4; ++mt) {
            #pragma unroll
            for (int half = 0; half < 2; ++half) {
                const int m = m0 + mbase + mt * 16 + quad + half * 8;
                #pragma unroll
                for (int nt = 0; nt < 8; ++nt) {
                    const int n = n0 + nbase + nt * 8 + tq * 2;
                    const float2 bv = *(const float2*)&bias[n];
                    float2 o;
                    o.x = c[mt][nt][half * 2 + 0] + bv.x;
                    o.y = c[mt][nt][half * 2 + 1] + bv.y;
                    *(float2*)&out[(size_t)m * NSTATE + n] = o;
                }
            }
        }
    }
}

// ---------------------------------------------------------------------------
// HMMA windowed attention, single-pass fp16: S = Q*K^T, ctx = P*V.
// 1 CTA per (qt, h, b); 4 warps. K/V double buffer via cp.async.
// ---------------------------------------------------------------------------
#define AP 144   // SMEM row pitch bytes (64 fp16 = 128B + 16B pad)

__global__ __launch_bounds__(128)
void attn_hmma()
{
    extern __shared__ char smraw[];
    const uint32_t sb   = smem_u32(smraw);
    const uint32_t Qh_s = sb;
    const uint32_t KVb  = sb + 64 * AP;   // [2 bufs][Kh, Vh][64*AP]

    const int tid  = threadIdx.x;
    const int lane = tid & 31;
    const int wid  = tid >> 5;
    const int qt = blockIdx.x;
    const int h  = blockIdx.y;
    const int b  = blockIdx.z;

    const size_t base = ((size_t)(b * HH + h) * SS) * DD;
    const char* qhp = (const char*)(g_qh + base) + (size_t)qt * 64 * 128;
    const char* kvsrc[2] = { (const char*)(g_kh + base), (const char*)(g_vh + base) };

    const int lr  = tid >> 1;
    const int lcb = (tid & 1) * 64;

    #pragma unroll
    for (int i = 0; i < 4; i++)
        CP_ASYNC16(Qh_s + lr * AP + lcb + i * 16, qhp + lr * 128 + lcb + i * 16);

    auto loadKV = [&](int kt, int p) {
        const uint32_t d0 = KVb + p * (2 * 64 * AP);
        #pragma unroll
        for (int t = 0; t < 2; t++)
            #pragma unroll
            for (int i = 0; i < 4; i++)
                CP_ASYNC16(d0 + t * 64 * AP + lr * AP + lcb + i * 16,
                           kvsrc[t] + ((size_t)kt * 64 + lr) * 128 + lcb + i * 16);
    };

    const int kt0 = (qt >= 4) ? (qt - 4) : 0;
    const int nkt = qt - kt0 + 1;
    loadKV(kt0, 0);
    CP_COMMIT();

    const int rowA = lane & 15, kbA = (lane >> 4) * 16;
    const int rowB = (lane & 7) + ((lane >> 4) & 1) * 8, kbB = ((lane >> 3) & 1) * 16;
    const int rowV = (lane & 7) + ((lane >> 3) & 1) * 8, cbV = ((lane >> 4) & 1) * 16;
    const int quad = lane >> 2, tq = lane & 3;

    uint32_t qah[4][4];
    float ctx[8][4];
    #pragma unroll
    for (int i = 0; i < 8; i++)
        #pragma unroll
        for (int j = 0; j < 4; j++) ctx[i][j] = 0.f;
    float rs0 = 0.f, rs1 = 0.f;

    for (int it = 0; it < nkt; ++it) {
        const int kt = kt0 + it;
        const int p  = it & 1;
        CP_WAIT(0);
        __syncthreads();
        if (it + 1 < nkt) {
            loadKV(kt + 1, p ^ 1);
            CP_COMMIT();
        }

        if (it == 0) {
            #pragma unroll
            for (int ks = 0; ks < 4; ks++) {
                const uint32_t off = (wid * 16 + rowA) * AP + ks * 32 + kbA;
                LDSM_X4(qah[ks][0], qah[ks][1], qah[ks][2], qah[ks][3], Qh_s + off);
            }
        }

        const uint32_t Kh = KVb + p * (2 * 64 * AP);
        const uint32_t Vh = Kh + 64 * AP;

        // ---- S = Q K^T ----
        float s[8][4];
        #pragma unroll
        for (int i = 0; i < 8; i++)
            #pragma unroll
            for (int j = 0; j < 4; j++) s[i][j] = 0.f;

        #pragma unroll
        for (int ks = 0; ks < 4; ks++) {
            #pragma unroll
            for (int h2 = 0; h2 < 2; ++h2) {
                uint32_t kh[2][4];
                #pragma unroll
                for (int ppl = 0; ppl < 2; ppl++) {
                    const int pp = h2 * 2 + ppl;
                    const uint32_t off = (pp * 16 + rowB) * AP + ks * 32 + kbB;
                    LDSM_X4(kh[ppl][0], kh[ppl][1], kh[ppl][2], kh[ppl][3], Kh + off);
                }
                #pragma unroll
                for (int ntl = 0; ntl < 4; ntl++) {
                    const int nt = h2 * 4 + ntl;
                    const int npl = ntl >> 1, w2 = (ntl & 1) * 2;
                    mma_fp16(s[nt], qah[ks], kh[npl][w2], kh[npl][w2 + 1]);
                }
            }
        }

        // ---- mask + exp + pack P into PV A-fragments ----
        uint32_t pah[4][4];
        const int i0 = qt * 64 + wid * 16 + quad;
        const int jb = kt * 64 + tq * 2;
        #pragma unroll
        for (int nt = 0; nt < 8; nt++) {
            const int j0 = jb + nt * 8;
            const int j1 = j0 + 1;
            float e0 = __expf(s[nt][0]);
            float e1 = __expf(s[nt][1]);
            float e2 = __expf(s[nt][2]);
            float e3 = __expf(s[nt][3]);
            { int df = i0 - j0;     if (df < 0 || df >= WIN) e0 = 0.f; }
            { int df = i0 - j1;     if (df < 0 || df >= WIN) e1 = 0.f; }
            { int df = i0 + 8 - j0; if (df < 0 || df >= WIN) e2 = 0.f; }
            { int df = i0 + 8 - j1; if (df < 0 || df >= WIN) e3 = 0.f; }
            rs0 += e0 + e1;
            rs1 += e2 + e3;
            const int ks = nt >> 1, r2 = (nt & 1) * 2;
            pah[ks][r2]     = pack_hi(e0, e1);
            pah[ks][r2 + 1] = pack_hi(e2, e3);
        }

        // ---- ctx += P V ----
        #pragma unroll
        for (int ks = 0; ks < 4; ks++) {
            #pragma unroll
            for (int h2 = 0; h2 < 2; ++h2) {
                uint32_t vh[2][4];
                #pragma unroll
                for (int ppl = 0; ppl < 2; ppl++) {
                    const int pp = h2 * 2 + ppl;
                    const uint32_t off = (ks * 16 + rowV) * AP + pp * 32 + cbV;
                    LDSM_X4_T(vh[ppl][0], vh[ppl][1], vh[ppl][2], vh[ppl][3], Vh + off);
                }
                #pragma unroll
                for (int ntl = 0; ntl < 4; ntl++) {
                    const int nt = h2 * 4 + ntl;
                    const int npl = ntl >> 1, w2 = (ntl & 1) * 2;
                    mma_fp16(ctx[nt], pah[ks], vh[npl][w2], vh[npl][w2 + 1]);
                }
            }
        }
    }

    rs0 += __shfl_xor_sync(0xFFFFFFFFu, rs0, 1);
    rs0 += __shfl_xor_sync(0xFFFFFFFFu, rs0, 2);
    rs1 += __shfl_xor_sync(0xFFFFFFFFu, rs1, 1);
    rs1 += __shfl_xor_sync(0xFFFFFFFFu, rs1, 2);
    const float inv0 = 1.0f / rs0;
    const float inv1 = 1.0f / rs1;

    const int s0 = qt * 64 + wid * 16 + quad;
    #pragma unroll
    for (int nt = 0; nt < 8; nt++) {
        const int d = nt * 8 + tq * 2;
        const size_t ix0 = ((size_t)(b * SS) + s0) * NSTATE + h * 64 + d;
        const size_t ix1 = ix0 + (size_t)8 * NSTATE;
        *(uint32_t*)&g_ch[ix0] = pack_hi(ctx[nt][0] * inv0, ctx[nt][1] * inv0);
        *(uint32_t*)&g_ch[ix1] = pack_hi(ctx[nt][2] * inv1, ctx[nt][3] * inv1);
    }
}

// ---------------------------------------------------------------------------
// Launch
// ---------------------------------------------------------------------------
extern "C" void kernel_launch(void* const* d_in, const int* in_sizes, int n_in,
                              void* d_out, int out_size)
{
    const float* x      = (const float*)d_in[0];
    const float* W_qkv  = (const float*)d_in[1];
    const float* b_qkv  = (const float*)d_in[2];
    const float* W_proj = (const float*)d_in[3];
    const float* b_proj = (const float*)d_in[4];
    float* out = (float*)d_out;

    const int GEMM_SMEM = 2 * BUFG;              // 73728 B (2 stages)
    const int ATTN_SMEM = (1 + 4) * 64 * AP;     // 46080 B
    cudaFuncSetAttribute(hmma_gemm<0>, cudaFuncAttributeMaxDynamicSharedMemorySize, GEMM_SMEM);
    cudaFuncSetAttribute(hmma_gemm<1>, cudaFuncAttributeMaxDynamicSharedMemorySize, GEMM_SMEM);
    cudaFuncSetAttribute(attn_hmma, cudaFuncAttributeMaxDynamicSharedMemorySize, ATTN_SMEM);

    const int NSPLIT = XQ4 + WQ4 + WP4;
    split_all<<<(NSPLIT + 255) / 256, 256>>>(x, W_qkv, W_proj);

    // QKV GEMM: [8192,1024] x [3072,1024]^T -> Q (scaled), K, V fp16
    hmma_gemm<0><<<dim3(3072 / 128, 8192 / 128), 128, GEMM_SMEM>>>(b_qkv, nullptr);

    // windowed attention -> ctx fp16
    attn_hmma<<<dim3(SS / 64, HH, BB), 128, ATTN_SMEM>>>();

    // proj GEMM: [8192,1024] x [1024,1024]^T -> out
    hmma_gemm<1><<<dim3(1024 / 128, 8192 / 128), 128, GEMM_SMEM>>>(b_proj, out);
}

// round 16
// speedup vs baseline: 1.0973x; 1.0098x over previous
#include <cuda_runtime.h>
#include <cuda_fp16.h>
#include <cstdint>
#include <math.h>

// Problem constants
#define BB      4
#define SS      2048
#define CC      1024
#define HH      16
#define DD      64
#define NSTATE  1024
#define WIN     256
#define SCALE_INV 0.125f   // 1/sqrt(64)

// ---------------------------------------------------------------------------
// Scratch (device globals; no runtime allocation)
// Pure fp16 1-pass pipeline (error model validated R7-R15: ~4.6e-4 total).
// ---------------------------------------------------------------------------
__device__ __half g_xh[BB * SS * CC];
__device__ __half g_wqh[3 * NSTATE * CC];
__device__ __half g_wph[CC * NSTATE];

// Q (pre-scaled by SCALE_INV), K, V: fp16, [B,H,S,D]
__device__ __half g_qh[BB * HH * SS * DD];
__device__ __half g_kh[BB * HH * SS * DD];
__device__ __half g_vh[BB * HH * SS * DD];

__device__ __half g_ch[BB * SS * NSTATE];   // ctx fp16

// ---------------------------------------------------------------------------
// PTX helpers (compute_80-safe: ldmatrix / mma.sync / cp.async)
// ---------------------------------------------------------------------------
__device__ __forceinline__ uint32_t smem_u32(const void* p) {
    uint32_t a;
    asm("{ .reg .u64 t; cvta.to.shared.u64 t, %1; cvt.u32.u64 %0, t; }"
        : "=r"(a) : "l"(p));
    return a;
}

#define CP_ASYNC16(dst, src) \
    asm volatile("cp.async.cg.shared.global [%0], [%1], 16;" \
        :: "r"(dst), "l"(src) : "memory")
#define CP_COMMIT() asm volatile("cp.async.commit_group;" ::: "memory")
#define CP_WAIT(n)  asm volatile("cp.async.wait_group %0;" :: "n"(n) : "memory")

#define LDSM_X4(r0, r1, r2, r3, addr) \
    asm volatile("ldmatrix.sync.aligned.m8n8.x4.shared.b16 {%0,%1,%2,%3}, [%4];" \
        : "=r"(r0), "=r"(r1), "=r"(r2), "=r"(r3) : "r"(addr))
#define LDSM_X4_T(r0, r1, r2, r3, addr) \
    asm volatile("ldmatrix.sync.aligned.m8n8.x4.trans.shared.b16 {%0,%1,%2,%3}, [%4];" \
        : "=r"(r0), "=r"(r1), "=r"(r2), "=r"(r3) : "r"(addr))

__device__ __forceinline__ void mma_fp16(float* c, const uint32_t* a,
                                         uint32_t b0, uint32_t b1) {
    asm volatile(
        "mma.sync.aligned.m16n8k16.row.col.f32.f16.f16.f32 "
        "{%0,%1,%2,%3}, {%4,%5,%6,%7}, {%8,%9}, {%0,%1,%2,%3};"
        : "+f"(c[0]), "+f"(c[1]), "+f"(c[2]), "+f"(c[3])
        : "r"(a[0]), "r"(a[1]), "r"(a[2]), "r"(a[3]), "r"(b0), "r"(b1));
}

__device__ __forceinline__ uint32_t pack_hi(float a, float b) {
    __half2 h = __floats2half2_rn(a, b);
    return *reinterpret_cast<uint32_t*>(&h);
}

// ---------------------------------------------------------------------------
// fused fp32 -> fp16 conversion for x, W_qkv, W_proj
// ---------------------------------------------------------------------------
#define XQ4   (BB * SS * CC / 4)
#define WQ4   (3 * NSTATE * CC / 4)
#define WP4   (CC * NSTATE / 4)

__global__ void split_all(const float* __restrict__ x,
                          const float* __restrict__ wq,
                          const float* __restrict__ wp)
{
    int i = blockIdx.x * blockDim.x + threadIdx.x;
    if (i >= XQ4 + WQ4 + WP4) return;

    const float* src;
    __half* dst;
    int j;
    if (i < XQ4)            { src = x;  dst = g_xh;  j = i; }
    else if (i < XQ4 + WQ4) { src = wq; dst = g_wqh; j = i - XQ4; }
    else                    { src = wp; dst = g_wph; j = i - XQ4 - WQ4; }
    float4 f = reinterpret_cast<const float4*>(src)[j];
    reinterpret_cast<uint32_t*>(dst)[2 * j]     = pack_hi(f.x, f.y);
    reinterpret_cast<uint32_t*>(dst)[2 * j + 1] = pack_hi(f.z, f.w);
}

// ---------------------------------------------------------------------------
// HMMA GEMM (R13 config — best measured): fp16 in, fp32 accum, 1 pass.
// CTA 128x128, K-chunk 64, 256 threads (8 warps, 4x2), warp tile 32x64,
// 2 CTAs/SM, 2-stage cp.async, in-register fragment double-buffering.
// ---------------------------------------------------------------------------
#define ROWB   144           // bytes per SMEM row (64 fp16 = 128B + 16B pad)
#define TILEB  (128 * ROWB)  // 18432 B per operand tile
#define BUFG   (2 * TILEB)   // A, B per stage
#define NCHK   (CC / 64)     // 16 K-chunks

template <int MODE>
__global__ __launch_bounds__(256, 2)
void hmma_gemm(const float* __restrict__ bias, float* __restrict__ out)
{
    extern __shared__ char dynsmem[];
    const uint32_t tb = smem_u32(dynsmem);

    const int tid  = threadIdx.x;
    const int wid  = tid >> 5;
    const int lane = tid & 31;
    const int m0 = blockIdx.y * 128;
    const int n0 = blockIdx.x * 128;

    const int wm = wid >> 1;
    const int wn = wid & 1;
    const int mbase = wm * 32;
    const int nbase = wn * 64;

    const int rowA  = lane & 15;
    const int koffA = (lane >> 4) * 16;
    const int rowB  = (lane & 7) + ((lane >> 4) & 1) * 8;
    const int koffB = ((lane >> 3) & 1) * 16;

    const __half* srcA = ((MODE == 0) ? g_xh : g_ch) + (size_t)m0 * CC;
    const __half* srcB = ((MODE == 0) ? g_wqh : g_wph) + (size_t)n0 * CC;

    const int ldrow0 = tid >> 3;      // 0..31
    const int lduc   = tid & 7;       // 8 x 16B columns

    float c[2][8][4];
    #pragma unroll
    for (int i = 0; i < 2; i++)
        #pragma unroll
        for (int j = 0; j < 8; j++)
            #pragma unroll
            for (int q = 0; q < 4; q++) c[i][j][q] = 0.f;

    auto issue = [&](int ch) {
        const int k0 = ch * 64;
        const uint32_t dstb = tb + (ch & 1) * BUFG;
        #pragma unroll
        for (int it = 0; it < 8; ++it) {
            const int tile = it >> 2;
            const int row  = ldrow0 + (it & 3) * 32;
            const __half* s = (tile ? srcB : srcA) + (size_t)row * CC + k0 + lduc * 8;
            const uint32_t d = dstb + tile * TILEB + row * ROWB + lduc * 16;
            CP_ASYNC16(d, s);
        }
    };

    issue(0);
    CP_COMMIT();

    uint32_t af[2][2][4];
    uint32_t bf[2][2][4];

    for (int ch = 0; ch < NCHK; ++ch) {
        CP_WAIT(0);
        __syncthreads();
        if (ch + 1 < NCHK) {
            issue(ch + 1);
            CP_COMMIT();
        }

        const uint32_t buf = tb + (ch & 1) * BUFG;
        const uint32_t Ah = buf;
        const uint32_t Bh = buf + TILEB;

        // prime step 0 fragments
        #pragma unroll
        for (int mt = 0; mt < 2; ++mt) {
            const uint32_t off = (mbase + mt * 16 + rowA) * ROWB + koffA;
            LDSM_X4(af[0][mt][0], af[0][mt][1], af[0][mt][2], af[0][mt][3], Ah + off);
        }
        #pragma unroll
        for (int npl = 0; npl < 2; ++npl) {
            const uint32_t off = (nbase + npl * 16 + rowB) * ROWB + koffB;
            LDSM_X4(bf[0][npl][0], bf[0][npl][1], bf[0][npl][2], bf[0][npl][3], Bh + off);
        }

        #pragma unroll
        for (int step = 0; step < 8; ++step) {
            const int ks   = step >> 1;
            const int h2   = step & 1;
            const int bpar = step & 1;
            const int apar = ks & 1;

            if (step < 7) {
                const int ns  = step + 1;
                const int nks = ns >> 1;
                const int nh2 = ns & 1;
                if (nks != ks) {
                    #pragma unroll
                    for (int mt = 0; mt < 2; ++mt) {
                        const uint32_t off =
                            (mbase + mt * 16 + rowA) * ROWB + nks * 32 + koffA;
                        LDSM_X4(af[nks & 1][mt][0], af[nks & 1][mt][1],
                                af[nks & 1][mt][2], af[nks & 1][mt][3], Ah + off);
                    }
                }
                #pragma unroll
                for (int npl = 0; npl < 2; ++npl) {
                    const uint32_t off =
                        (nbase + (nh2 * 2 + npl) * 16 + rowB) * ROWB + nks * 32 + koffB;
                    LDSM_X4(bf[ns & 1][npl][0], bf[ns & 1][npl][1],
                            bf[ns & 1][npl][2], bf[ns & 1][npl][3], Bh + off);
                }
            }

            #pragma unroll
            for (int mt = 0; mt < 2; ++mt) {
                #pragma unroll
                for (int ntl = 0; ntl < 4; ++ntl) {
                    const int nt  = h2 * 4 + ntl;
                    const int npl = ntl >> 1;
                    const int w2  = (ntl & 1) * 2;
                    mma_fp16(c[mt][nt], af[apar][mt],
                             bf[bpar][npl][w2], bf[bpar][npl][w2 + 1]);
                }
            }
        }
    }

    // ---- epilogue ----
    const int quad = lane >> 2;
    const int tq   = lane & 3;

    if (MODE == 0) {
        const int sec = n0 >> 10;                     // 0=q, 1=k, 2=v
        const int h   = ((n0 + nbase) & 1023) >> 6;
        const float sc = (sec == 0) ? SCALE_INV : 1.0f;
        __half* dst = (sec == 0) ? g_qh : (sec == 1) ? g_kh : g_vh;
        #pragma unroll
        for (int mt = 0; mt < 2; ++mt) {
            #pragma unroll
            for (int half = 0; half < 2; ++half) {
                const int m = m0 + mbase + mt * 16 + quad + half * 8;
                const int b = m >> 11;
                const int s = m & 2047;
                const size_t rowp = ((size_t)((b * HH + h) * SS + s)) * DD;
                #pragma unroll
                for (int nt = 0; nt < 8; ++nt) {
                    const int n = n0 + nbase + nt * 8 + tq * 2;
                    const int d = nt * 8 + tq * 2;
                    const float2 bv = *(const float2*)&bias[n];
                    *(uint32_t*)&dst[rowp + d] =
                        pack_hi((c[mt][nt][half * 2 + 0] + bv.x) * sc,
                                (c[mt][nt][half * 2 + 1] + bv.y) * sc);
                }
            }
        }
    } else {
        #pragma unroll
        for (int mt = 0; mt < 2; ++mt) {
            #pragma unroll
            for (int half = 0; half < 2; ++half) {
                const int m = m0 + mbase + mt * 16 + quad + half * 8;
                #pragma unroll
                for (int nt = 0; nt < 8; ++nt) {
                    const int n = n0 + nbase + nt * 8 + tq * 2;
                    const float2 bv = *(const float2*)&bias[n];
                    float2 o;
                    o.x = c[mt][nt][half * 2 + 0] + bv.x;
                    o.y = c[mt][nt][half * 2 + 1] + bv.y;
                    *(float2*)&out[(size_t)m * NSTATE + n] = o;
                }
            }
        }
    }
}

// ---------------------------------------------------------------------------
// HMMA windowed attention, single-pass fp16.
// NEW: 128 q-rows per CTA (2 q-tiles), 256 threads / 8 warps.
// Warps 0-3 own q-tile 2*bx, warps 4-7 own 2*bx+1; one shared K/V stream
// covering the union window -> K/V global+smem traffic per MMA halves.
// Each warp computes only its active kt iterations (uniform barriers).
// ---------------------------------------------------------------------------
#define AP 144   // SMEM row pitch bytes (64 fp16 = 128B + 16B pad)

__global__ __launch_bounds__(256)
void attn_hmma()
{
    extern __shared__ char smraw[];
    const uint32_t sb   = smem_u32(smraw);
    const uint32_t Qh_s = sb;                  // 128 rows
    const uint32_t KVb  = sb + 128 * AP;       // [2 bufs][Kh, Vh][64*AP]

    const int tid  = threadIdx.x;
    const int lane = tid & 31;
    const int wid  = tid >> 5;                 // 0..7
    const int bx = blockIdx.x;                 // 0..15 (128 q rows each)
    const int h  = blockIdx.y;
    const int b  = blockIdx.z;

    const int qtA = bx * 2;                    // first q-tile of this CTA
    const int wqt = qtA + (wid >> 2);          // this warp's q-tile
    const int wrow = (wid >> 2) * 64 + (wid & 3) * 16;   // warp's first row in Q smem

    const size_t base = ((size_t)(b * HH + h) * SS) * DD;
    const char* qhp = (const char*)(g_qh + base) + (size_t)bx * 128 * 128;
    const char* kvsrc[2] = { (const char*)(g_kh + base), (const char*)(g_vh + base) };

    // Q load: 128 rows x 128B, 256 threads x 4 cp.async
    {
        const int lr  = tid >> 1;              // 0..127
        const int lcb = (tid & 1) * 64;
        #pragma unroll
        for (int i = 0; i < 4; i++)
            CP_ASYNC16(Qh_s + lr * AP + lcb + i * 16, qhp + lr * 128 + lcb + i * 16);
    }
    // K/V tile load: 2 tiles x 64 rows x 128B, 256 threads x 2x2 cp.async
    auto loadKV = [&](int kt, int p) {
        const uint32_t d0 = KVb + p * (2 * 64 * AP);
        const int row = tid >> 2;              // 0..63
        const int cb  = (tid & 3) * 32;
        #pragma unroll
        for (int t = 0; t < 2; t++)
            #pragma unroll
            for (int i = 0; i < 2; i++)
                CP_ASYNC16(d0 + t * 64 * AP + row * AP + cb + i * 16,
                           kvsrc[t] + ((size_t)kt * 64 + row) * 128 + cb + i * 16);
    };

    const int kt0  = (qtA >= 4) ? (qtA - 4) : 0;
    const int nkt  = (qtA + 1) - kt0 + 1;
    loadKV(kt0, 0);
    CP_COMMIT();

    const int rowA = lane & 15, kbA = (lane >> 4) * 16;
    const int rowB = (lane & 7) + ((lane >> 4) & 1) * 8, kbB = ((lane >> 3) & 1) * 16;
    const int rowV = (lane & 7) + ((lane >> 3) & 1) * 8, cbV = ((lane >> 4) & 1) * 16;
    const int quad = lane >> 2, tq = lane & 3;

    uint32_t qah[4][4];
    float ctx[8][4];
    #pragma unroll
    for (int i = 0; i < 8; i++)
        #pragma unroll
        for (int j = 0; j < 4; j++) ctx[i][j] = 0.f;
    float rs0 = 0.f, rs1 = 0.f;

    for (int it = 0; it < nkt; ++it) {
        const int kt = kt0 + it;
        const int p  = it & 1;
        CP_WAIT(0);
        __syncthreads();
        if (it + 1 < nkt) {
            loadKV(kt + 1, p ^ 1);
            CP_COMMIT();
        }

        if (it == 0) {
            #pragma unroll
            for (int ks = 0; ks < 4; ks++) {
                const uint32_t off = (wrow + rowA) * AP + ks * 32 + kbA;
                LDSM_X4(qah[ks][0], qah[ks][1], qah[ks][2], qah[ks][3], Qh_s + off);
            }
        }

        // window activity for this warp's q-tile
        if (kt < wqt - 4 || kt > wqt) continue;

        const uint32_t Kh = KVb + p * (2 * 64 * AP);
        const uint32_t Vh = Kh + 64 * AP;

        // ---- S = Q K^T ----
        float s[8][4];
        #pragma unroll
        for (int i = 0; i < 8; i++)
            #pragma unroll
            for (int j = 0; j < 4; j++) s[i][j] = 0.f;

        #pragma unroll
        for (int ks = 0; ks < 4; ks++) {
            #pragma unroll
            for (int h2 = 0; h2 < 2; ++h2) {
                uint32_t kh[2][4];
                #pragma unroll
                for (int ppl = 0; ppl < 2; ppl++) {
                    const int pp = h2 * 2 + ppl;
                    const uint32_t off = (pp * 16 + rowB) * AP + ks * 32 + kbB;
                    LDSM_X4(kh[ppl][0], kh[ppl][1], kh[ppl][2], kh[ppl][3], Kh + off);
                }
                #pragma unroll
                for (int ntl = 0; ntl < 4; ntl++) {
                    const int nt = h2 * 4 + ntl;
                    const int npl = ntl >> 1, w2 = (ntl & 1) * 2;
                    mma_fp16(s[nt], qah[ks], kh[npl][w2], kh[npl][w2 + 1]);
                }
            }
        }

        // ---- mask + exp + pack P into PV A-fragments ----
        uint32_t pah[4][4];
        const int i0 = bx * 128 + wrow + quad;
        const int jb = kt * 64 + tq * 2;
        #pragma unroll
        for (int nt = 0; nt < 8; nt++) {
            const int j0 = jb + nt * 8;
            const int j1 = j0 + 1;
            float e0 = __expf(s[nt][0]);
            float e1 = __expf(s[nt][1]);
            float e2 = __expf(s[nt][2]);
            float e3 = __expf(s[nt][3]);
            { int df = i0 - j0;     if (df < 0 || df >= WIN) e0 = 0.f; }
            { int df = i0 - j1;     if (df < 0 || df >= WIN) e1 = 0.f; }
            { int df = i0 + 8 - j0; if (df < 0 || df >= WIN) e2 = 0.f; }
            { int df = i0 + 8 - j1; if (df < 0 || df >= WIN) e3 = 0.f; }
            rs0 += e0 + e1;
            rs1 += e2 + e3;
            const int ks = nt >> 1, r2 = (nt & 1) * 2;
            pah[ks][r2]     = pack_hi(e0, e1);
            pah[ks][r2 + 1] = pack_hi(e2, e3);
        }

        // ---- ctx += P V ----
        #pragma unroll
        for (int ks = 0; ks < 4; ks++) {
            #pragma unroll
            for (int h2 = 0; h2 < 2; ++h2) {
                uint32_t vh[2][4];
                #pragma unroll
                for (int ppl = 0; ppl < 2; ppl++) {
                    const int pp = h2 * 2 + ppl;
                    const uint32_t off = (ks * 16 + rowV) * AP + pp * 32 + cbV;
                    LDSM_X4_T(vh[ppl][0], vh[ppl][1], vh[ppl][2], vh[ppl][3], Vh + off);
                }
                #pragma unroll
                for (int ntl = 0; ntl < 4; ntl++) {
                    const int nt = h2 * 4 + ntl;
                    const int npl = ntl >> 1, w2 = (ntl & 1) * 2;
                    mma_fp16(ctx[nt], pah[ks], vh[npl][w2], vh[npl][w2 + 1]);
                }
            }
        }
    }

    rs0 += __shfl_xor_sync(0xFFFFFFFFu, rs0, 1);
    rs0 += __shfl_xor_sync(0xFFFFFFFFu, rs0, 2);
    rs1 += __shfl_xor_sync(0xFFFFFFFFu, rs1, 1);
    rs1 += __shfl_xor_sync(0xFFFFFFFFu, rs1, 2);
    const float inv0 = 1.0f / rs0;
    const float inv1 = 1.0f / rs1;

    const int s0 = bx * 128 + wrow + quad;
    #pragma unroll
    for (int nt = 0; nt < 8; nt++) {
        const int d = nt * 8 + tq * 2;
        const size_t ix0 = ((size_t)(b * SS) + s0) * NSTATE + h * 64 + d;
        const size_t ix1 = ix0 + (size_t)8 * NSTATE;
        *(uint32_t*)&g_ch[ix0] = pack_hi(ctx[nt][0] * inv0, ctx[nt][1] * inv0);
        *(uint32_t*)&g_ch[ix1] = pack_hi(ctx[nt][2] * inv1, ctx[nt][3] * inv1);
    }
}

// ---------------------------------------------------------------------------
// Launch
// ---------------------------------------------------------------------------
extern "C" void kernel_launch(void* const* d_in, const int* in_sizes, int n_in,
                              void* d_out, int out_size)
{
    const float* x      = (const float*)d_in[0];
    const float* W_qkv  = (const float*)d_in[1];
    const float* b_qkv  = (const float*)d_in[2];
    const float* W_proj = (const float*)d_in[3];
    const float* b_proj = (const float*)d_in[4];
    float* out = (float*)d_out;

    const int GEMM_SMEM = 2 * BUFG;                    // 73728 B
    const int ATTN_SMEM = 128 * AP + 4 * 64 * AP;      // 55296 B
    cudaFuncSetAttribute(hmma_gemm<0>, cudaFuncAttributeMaxDynamicSharedMemorySize, GEMM_SMEM);
    cudaFuncSetAttribute(hmma_gemm<1>, cudaFuncAttributeMaxDynamicSharedMemorySize, GEMM_SMEM);
    cudaFuncSetAttribute(attn_hmma, cudaFuncAttributeMaxDynamicSharedMemorySize, ATTN_SMEM);

    const int NSPLIT = XQ4 + WQ4 + WP4;
    split_all<<<(NSPLIT + 255) / 256, 256>>>(x, W_qkv, W_proj);

    // QKV GEMM: [8192,1024] x [3072,1024]^T -> Q (scaled), K, V fp16
    hmma_gemm<0><<<dim3(3072 / 128, 8192 / 128), 256, GEMM_SMEM>>>(b_qkv, nullptr);

    // windowed attention -> ctx fp16 (128 q-rows per CTA)
    attn_hmma<<<dim3(SS / 128, HH, BB), 256, ATTN_SMEM>>>();

    // proj GEMM: [8192,1024] x [1024,1024]^T -> out
    hmma_gemm<1><<<dim3(1024 / 128, 8192 / 128), 256, GEMM_SMEM>>>(b_proj, out);
}